// round 6
// baseline (speedup 1.0000x reference)
#include <cuda_runtime.h>
#include <math.h>

// VectorQuantizer: N=65536 (64x32x32 BHWC-flat), C=64, K=1024.
// Output (float32): [quantized 4194304][vq_loss 1][indices 65536][perplexity 1]
// Numerics verified bit-exact in R1/R5.

#define NPTS   65536
#define KC     1024
#define CD     64
#define HW     1024
#define MT     128
#define KCH    64
#define NCHUNK (KC / KCH)

#define XSTRIDE 132          // xs pitch [c][p]
#define EP2     160          // es pitch [c][dup'd skewed codes]
#define SMEM_FLOATS (CD*XSTRIDE + CD*EP2 + 128)
#define SMEM_BYTES  (SMEM_FLOATS * 4)     // 75,264 B -> 2 blocks/SM

#define OFF_LOSS  4194304
#define OFF_IDX   4194305
#define OFF_PERP  4259841

typedef unsigned long long u64;

__device__ float        g_esq[KC];
__device__ int          g_idx[NPTS];
__device__ unsigned int g_hist[KC];
__device__ double       g_loss;

__device__ __forceinline__ void unpack2(u64 v, float &lo, float &hi) {
    asm("mov.b64 {%0, %1}, %2;" : "=f"(lo), "=f"(hi) : "l"(v));
}
// packed fp32x2 FMA: each lane is IEEE-rn fp32 FMA (bit-identical to scalar FFMA)
__device__ __forceinline__ void ffma2(u64 &acc, u64 a, u64 b) {
    asm("fma.rn.f32x2 %0, %1, %2, %0;" : "+l"(acc) : "l"(a), "l"(b));
}

// ---------------- init ----------------
__global__ void vq_init() {
    int t = blockIdx.x * blockDim.x + threadIdx.x;
    if (t < KC) g_hist[t] = 0u;
    if (t == 0) g_loss = 0.0;
}

// ---------------- esq ----------------
__global__ void vq_esq(const float* __restrict__ emb) {
    int k = blockIdx.x * blockDim.x + threadIdx.x;
    if (k < KC) {
        float s = 0.0f;
        const float* er = emb + (size_t)k * CD;
        #pragma unroll
        for (int c = 0; c < CD; ++c) {
            float e = er[c];
            s = __fadd_rn(s, __fmul_rn(e, e));
        }
        g_esq[k] = s;
    }
}

// ---------------- main: distances + argmin ----------------
__global__ void __launch_bounds__(256) vq_main(const float* __restrict__ inputs,
                                               const float* __restrict__ emb,
                                               float* __restrict__ outIdxF) {
    extern __shared__ float sm[];
    float* xs  = sm;                     // [CD][XSTRIDE]  xs[c*XSTRIDE + p]
    float* es  = sm + CD * XSTRIDE;      // [CD][EP2]      dup'd+skewed E chunk
    float* as_ = es + CD * EP2;          // [128]

    const int t  = threadIdx.x;
    const int tr = t >> 4;    // 0..15 point group (8 pts each)
    const int tc = t & 15;    // 0..15 code lane (4 codes each)
    const int n0 = blockIdx.x * MT;
    const int b  = n0 >> 10;
    const int p0 = n0 & 1023;
    const float* xbase = inputs + (size_t)b * (CD * HW) + p0;

    // load x tile (transposed into [c][p])
    #pragma unroll
    for (int j = 0; j < 8; ++j) {
        int q  = t + j * 256;
        int c  = q >> 5;
        int i4 = (q & 31) << 2;
        float4 v = *reinterpret_cast<const float4*>(xbase + (size_t)c * HW + i4);
        *reinterpret_cast<float4*>(&xs[c * XSTRIDE + i4]) = v;
    }
    __syncthreads();

    // a = ||x||^2 : strictly sequential fp32
    if (t < MT) {
        float s = 0.0f;
        #pragma unroll
        for (int c = 0; c < CD; ++c) {
            float xv = xs[c * XSTRIDE + t];
            s = __fadd_rn(s, __fmul_rn(xv, xv));
        }
        as_[t] = s;
    }
    __syncthreads();

    float a_[8];
    #pragma unroll
    for (int i = 0; i < 8; ++i) a_[i] = as_[tr * 8 + i];

    float bestv[8];
    int   besti[8];
    #pragma unroll
    for (int i = 0; i < 8; ++i) { bestv[i] = __int_as_float(0x7f800000); besti[i] = 0x7fffffff; }

    // staging constants (loop-invariant): this thread writes code k's 4 channels
    const int sk = t & 63;                                        // code within chunk
    const int sF = 8 * (sk >> 2) + 4 * (sk >> 3) + 2 * (sk & 3);  // skewed dup position
    // consumer base: lane tc's 4 codes, dup'd, skewed
    const float* er = es + 8 * tc + 4 * (tc >> 1);
    const float* xr = xs + 8 * tr;

    #pragma unroll 1
    for (int kc = 0; kc < NCHUNK; ++kc) {
        __syncthreads();   // previous chunk's es readers done
        // stage dup'd E chunk: es[c][F(k)+{0,1}] = e[kc*64+k][c]
        #pragma unroll
        for (int j = 0; j < 4; ++j) {
            int cg = (t >> 6) + 4 * j;   // 0..15
            float4 v = __ldg(reinterpret_cast<const float4*>(
                emb + (size_t)(kc * KCH + sk) * CD + 4 * cg));
            *reinterpret_cast<float2*>(&es[(4 * cg + 0) * EP2 + sF]) = make_float2(v.x, v.x);
            *reinterpret_cast<float2*>(&es[(4 * cg + 1) * EP2 + sF]) = make_float2(v.y, v.y);
            *reinterpret_cast<float2*>(&es[(4 * cg + 2) * EP2 + sF]) = make_float2(v.z, v.z);
            *reinterpret_cast<float2*>(&es[(4 * cg + 3) * EP2 + sF]) = make_float2(v.w, v.w);
        }
        __syncthreads();   // es ready

        u64 acc[4][4];     // [code q][point-pair i]
        #pragma unroll
        for (int q = 0; q < 4; ++q)
            #pragma unroll
            for (int i = 0; i < 4; ++i) acc[q][i] = 0ULL;

        #pragma unroll 4
        for (int c = 0; c < CD; ++c) {
            // E: 4 codes dup'd -> 2 LDS.128: ((e0,e0),(e1,e1)) and ((e2,e2),(e3,e3))
            ulonglong2 E01 = *reinterpret_cast<const ulonglong2*>(er + c * EP2);
            ulonglong2 E23 = *reinterpret_cast<const ulonglong2*>(er + c * EP2 + 4);
            // X: 8 points as 4 natural pairs (broadcast across tc)
            ulonglong2 Xa = *reinterpret_cast<const ulonglong2*>(xr + c * XSTRIDE);
            ulonglong2 Xb = *reinterpret_cast<const ulonglong2*>(xr + c * XSTRIDE + 4);
            ffma2(acc[0][0], E01.x, Xa.x); ffma2(acc[0][1], E01.x, Xa.y);
            ffma2(acc[0][2], E01.x, Xb.x); ffma2(acc[0][3], E01.x, Xb.y);
            ffma2(acc[1][0], E01.y, Xa.x); ffma2(acc[1][1], E01.y, Xa.y);
            ffma2(acc[1][2], E01.y, Xb.x); ffma2(acc[1][3], E01.y, Xb.y);
            ffma2(acc[2][0], E23.x, Xa.x); ffma2(acc[2][1], E23.x, Xa.y);
            ffma2(acc[2][2], E23.x, Xb.x); ffma2(acc[2][3], E23.x, Xb.y);
            ffma2(acc[3][0], E23.y, Xa.x); ffma2(acc[3][1], E23.y, Xa.y);
            ffma2(acc[3][2], E23.y, Xb.x); ffma2(acc[3][3], E23.y, Xb.y);
        }

        // epilogue: d = (a - 2*dot) + esq; k strictly ascending per lane -> '<'
        float4 eq = __ldg(reinterpret_cast<const float4*>(&g_esq[kc * KCH + 4 * tc]));
        #pragma unroll
        for (int q = 0; q < 4; ++q) {
            int k = kc * KCH + 4 * tc + q;
            float esq = (q == 0) ? eq.x : (q == 1) ? eq.y : (q == 2) ? eq.z : eq.w;
            #pragma unroll
            for (int i = 0; i < 4; ++i) {
                float d0, d1; unpack2(acc[q][i], d0, d1);
                int ii = i * 2;
                float dd0 = __fadd_rn(__fsub_rn(a_[ii],     __fmul_rn(2.0f, d0)), esq);
                float dd1 = __fadd_rn(__fsub_rn(a_[ii + 1], __fmul_rn(2.0f, d1)), esq);
                if (dd0 < bestv[ii])     { bestv[ii]     = dd0; besti[ii]     = k; }
                if (dd1 < bestv[ii + 1]) { bestv[ii + 1] = dd1; besti[ii + 1] = k; }
            }
        }
    }

    // cross-lane argmin over the 16 code lanes (first-index ties)
    #pragma unroll
    for (int off = 1; off < 16; off <<= 1) {
        #pragma unroll
        for (int i = 0; i < 8; ++i) {
            float ov = __shfl_xor_sync(0xffffffffu, bestv[i], off);
            int   oi = __shfl_xor_sync(0xffffffffu, besti[i], off);
            if (ov < bestv[i] || (ov == bestv[i] && oi < besti[i])) { bestv[i] = ov; besti[i] = oi; }
        }
    }
    if (tc == 0) {
        #pragma unroll
        for (int i = 0; i < 8; ++i) {
            int n = n0 + tr * 8 + i;
            g_idx[n]   = besti[i];
            outIdxF[n] = (float)besti[i];
            atomicAdd(&g_hist[besti[i]], 1u);
        }
    }
}

// ---------------- quantize + loss (coalesced via smem transpose) ----------------
__global__ void __launch_bounds__(256) vq_quant(const float* __restrict__ inputs,
                                                const float* __restrict__ emb,
                                                float* __restrict__ outQ) {
    __shared__ float  xt[CD * 129];
    __shared__ double red[256];

    const int t  = threadIdx.x;
    const int n0 = blockIdx.x * MT;
    const int b  = n0 >> 10;
    const int p0 = n0 & 1023;
    const float* xbase = inputs + (size_t)b * (CD * HW) + p0;

    #pragma unroll
    for (int j = 0; j < 8; ++j) {
        int q = t + j * 256;
        int c = q >> 5;
        int g = q & 31;
        float4 v = *reinterpret_cast<const float4*>(xbase + (size_t)c * HW + 4 * g);
        xt[c * 129 + 4 * g + 0] = v.x;
        xt[c * 129 + 4 * g + 1] = v.y;
        xt[c * 129 + 4 * g + 2] = v.z;
        xt[c * 129 + 4 * g + 3] = v.w;
    }
    __syncthreads();

    const int pc = t & 15;
    const int pg = t >> 4;
    double s = 0.0;

    #pragma unroll
    for (int i = 0; i < 8; ++i) {
        int p = pg * 8 + i;
        int n = n0 + p;
        int ki = g_idx[n];
        float4 qv = __ldg(reinterpret_cast<const float4*>(emb + (size_t)ki * CD + 4 * pc));
        float x0 = xt[(4 * pc + 0) * 129 + p];
        float x1 = xt[(4 * pc + 1) * 129 + p];
        float x2 = xt[(4 * pc + 2) * 129 + p];
        float x3 = xt[(4 * pc + 3) * 129 + p];

        float e0 = __fsub_rn(qv.x, x0);
        float e1 = __fsub_rn(qv.y, x1);
        float e2 = __fsub_rn(qv.z, x2);
        float e3 = __fsub_rn(qv.w, x3);

        float4 o;  // straight-through: x + (q - x)
        o.x = __fadd_rn(x0, e0);
        o.y = __fadd_rn(x1, e1);
        o.z = __fadd_rn(x2, e2);
        o.w = __fadd_rn(x3, e3);
        *reinterpret_cast<float4*>(outQ + (size_t)n * CD + 4 * pc) = o;

        s += (double)__fmul_rn(e0, e0) + (double)__fmul_rn(e1, e1)
           + (double)__fmul_rn(e2, e2) + (double)__fmul_rn(e3, e3);
    }

    red[t] = s;
    __syncthreads();
    for (int off = 128; off > 0; off >>= 1) {
        if (t < off) red[t] += red[t + off];
        __syncthreads();
    }
    if (t == 0) atomicAdd(&g_loss, red[0]);
}

// ---------------- finalize ----------------
__global__ void vq_final(float* __restrict__ out) {
    __shared__ double red[256];
    int t = threadIdx.x;
    double s = 0.0;
    for (int k = t; k < KC; k += 256) {
        float cnt = (float)g_hist[k];
        float pr  = __fmul_rn(cnt, 1.0f / 65536.0f);
        float lg  = logf(__fadd_rn(pr, 1e-10f));
        s += (double)__fmul_rn(pr, lg);
    }
    red[t] = s;
    __syncthreads();
    for (int off = 128; off > 0; off >>= 1) {
        if (t < off) red[t] += red[t + off];
        __syncthreads();
    }
    if (t == 0) {
        float m = (float)(g_loss / 4194304.0);
        out[OFF_LOSS] = __fadd_rn(m, __fmul_rn(0.25f, m));
        out[OFF_PERP] = expf(-(float)red[0]);
    }
}

extern "C" void kernel_launch(void* const* d_in, const int* in_sizes, int n_in,
                              void* d_out, int out_size) {
    const float* inputs = (const float*)d_in[0];
    const float* emb    = (const float*)d_in[1];
    if (n_in >= 2 && in_sizes[0] == KC * CD && in_sizes[1] == NPTS * CD) {
        const float* tmp = inputs; inputs = emb; emb = tmp;
    }
    float* out = (float*)d_out;

    cudaFuncSetAttribute(vq_main, cudaFuncAttributeMaxDynamicSharedMemorySize, SMEM_BYTES);

    vq_init<<<1, 1024>>>();
    vq_esq<<<KC / 256, 256>>>(emb);
    vq_main<<<NPTS / MT, 256, SMEM_BYTES>>>(inputs, emb, out + OFF_IDX);
    vq_quant<<<NPTS / MT, 256>>>(inputs, emb, out);
    vq_final<<<1, 256>>>(out);
}

// round 7
// speedup vs baseline: 2.1420x; 2.1420x over previous
#include <cuda_runtime.h>
#include <math.h>

// VectorQuantizer: N=65536 (64x32x32 BHWC-flat), C=64, K=1024.
// Output (float32): [quantized 4194304][vq_loss 1][indices 65536][perplexity 1]
// Numerics verified bit-exact in R1/R5. Mainloop layout = R5 (measured best:
// sits exactly at the joint fma/crossbar roofline, 64 B per ffma2).

#define NPTS   65536
#define KC     1024
#define CD     64
#define HW     1024
#define MT     128
#define XSTRIDE 132
#define ESTRIDE 68
#define SMEM_FLOATS (CD*XSTRIDE + 128*ESTRIDE + 128)
#define SMEM_BYTES  (SMEM_FLOATS * 4)

#define OFF_LOSS  4194304
#define OFF_IDX   4194305
#define OFF_PERP  4259841

typedef unsigned long long u64;

__device__ float        g_esq[KC];
__device__ unsigned int g_hist[KC];
__device__ double       g_loss;

__device__ __forceinline__ u64 pack_dup(float x) {
    u64 r; asm("mov.b64 %0, {%1, %1};" : "=l"(r) : "f"(x)); return r;
}
__device__ __forceinline__ void unpack2(u64 v, float &lo, float &hi) {
    asm("mov.b64 {%0, %1}, %2;" : "=f"(lo), "=f"(hi) : "l"(v));
}
// packed fp32x2 FMA: each lane is IEEE-rn fp32 FMA (bit-identical to scalar FFMA)
__device__ __forceinline__ void ffma2(u64 &acc, u64 a, u64 b) {
    asm("fma.rn.f32x2 %0, %1, %2, %0;" : "+l"(acc) : "l"(a), "l"(b));
}

// ---------------- init ----------------
__global__ void vq_init() {
    int t = blockIdx.x * blockDim.x + threadIdx.x;
    if (t < KC) g_hist[t] = 0u;
    if (t == 0) g_loss = 0.0;
}

// ---------------- esq ----------------
__global__ void vq_esq(const float* __restrict__ emb) {
    int k = blockIdx.x * blockDim.x + threadIdx.x;
    if (k < KC) {
        float s = 0.0f;
        const float* er = emb + (size_t)k * CD;
        #pragma unroll
        for (int c = 0; c < CD; ++c) {
            float e = er[c];
            s = __fadd_rn(s, __fmul_rn(e, e));
        }
        g_esq[k] = s;
    }
}

// ------- fused: distances + argmin + quantize + loss + hist -------
__global__ void __launch_bounds__(256) vq_main(const float* __restrict__ inputs,
                                               const float* __restrict__ emb,
                                               float* __restrict__ out) {
    extern __shared__ float sm[];
    float* xs  = sm;                     // [CD][XSTRIDE]   xs[c*XSTRIDE + p]
    float* es  = sm + CD * XSTRIDE;      // [128][ESTRIDE]  es[kk*ESTRIDE + c]
    float* as_ = es + 128 * ESTRIDE;     // [128]; reused as idxs[] in the tail
    int*   idxs = (int*)as_;
    double* red = (double*)es;           // tail block-reduce scratch (es is dead then)

    const int t  = threadIdx.x;
    const int tr = t >> 4;    // 0..15 point group (8 pts each)
    const int tc = t & 15;    // 0..15 code lane
    const int n0 = blockIdx.x * MT;
    const int b  = n0 >> 10;
    const int p0 = n0 & 1023;
    const float* xbase = inputs + (size_t)b * (CD * HW) + p0;

    // load x tile (transposed into [c][p])
    #pragma unroll
    for (int j = 0; j < 8; ++j) {
        int q  = t + j * 256;
        int c  = q >> 5;
        int i4 = (q & 31) << 2;
        float4 v = *reinterpret_cast<const float4*>(xbase + (size_t)c * HW + i4);
        *reinterpret_cast<float4*>(&xs[c * XSTRIDE + i4]) = v;
    }
    __syncthreads();

    // a = ||x||^2 : strictly sequential fp32
    if (t < MT) {
        float s = 0.0f;
        #pragma unroll
        for (int c = 0; c < CD; ++c) {
            float xv = xs[c * XSTRIDE + t];
            s = __fadd_rn(s, __fmul_rn(xv, xv));
        }
        as_[t] = s;
    }
    __syncthreads();

    // hoist point norms into regs (as_ is dead after this; reused as idxs later)
    float a_[8];
    #pragma unroll
    for (int i = 0; i < 8; ++i) a_[i] = as_[tr * 8 + i];

    float bestv[8];
    int   besti[8];
    #pragma unroll
    for (int i = 0; i < 8; ++i) { bestv[i] = __int_as_float(0x7f800000); besti[i] = 0x7fffffff; }

    #pragma unroll 1
    for (int kc = 0; kc < 8; ++kc) {
        __syncthreads();   // es reuse
        // load e chunk: es[kk][c] = emb[(kc*128+kk)*64 + c]
        #pragma unroll
        for (int j = 0; j < 8; ++j) {
            int q  = t + j * 256;
            int kk = q >> 4;
            int cg = (q & 15) << 2;
            float4 v = *reinterpret_cast<const float4*>(emb + (size_t)(kc * 128 + kk) * CD + cg);
            *reinterpret_cast<float4*>(&es[kk * ESTRIDE + cg]) = v;
        }
        __syncthreads();

        u64 acc[8][4];
        #pragma unroll
        for (int j = 0; j < 8; ++j)
            #pragma unroll
            for (int i = 0; i < 4; ++i) acc[j][i] = 0ULL;

        #pragma unroll 4
        for (int c4 = 0; c4 < CD; c4 += 4) {
            float4 ef[8];
            #pragma unroll
            for (int j = 0; j < 8; ++j)
                ef[j] = *reinterpret_cast<const float4*>(&es[(j * 16 + tc) * ESTRIDE + c4]);
            #pragma unroll
            for (int cc = 0; cc < 4; ++cc) {
                const float* xr = &xs[(c4 + cc) * XSTRIDE + tr * 8];
                ulonglong2 Xa = *reinterpret_cast<const ulonglong2*>(xr);
                ulonglong2 Xb = *reinterpret_cast<const ulonglong2*>(xr + 4);
                #pragma unroll
                for (int j = 0; j < 8; ++j) {
                    float ev = (cc == 0) ? ef[j].x : (cc == 1) ? ef[j].y : (cc == 2) ? ef[j].z : ef[j].w;
                    u64 ed = pack_dup(ev);
                    ffma2(acc[j][0], ed, Xa.x);
                    ffma2(acc[j][1], ed, Xa.y);
                    ffma2(acc[j][2], ed, Xb.x);
                    ffma2(acc[j][3], ed, Xb.y);
                }
            }
        }

        // epilogue: d = (a - 2*dot) + esq; k strictly ascending per lane -> strict '<'
        #pragma unroll
        for (int j = 0; j < 8; ++j) {
            int k = kc * 128 + j * 16 + tc;
            float esq = __ldg(&g_esq[k]);
            #pragma unroll
            for (int i = 0; i < 4; ++i) {
                float d0, d1; unpack2(acc[j][i], d0, d1);
                int ii = i * 2;
                float dd0 = __fadd_rn(__fsub_rn(a_[ii],     __fmul_rn(2.0f, d0)), esq);
                float dd1 = __fadd_rn(__fsub_rn(a_[ii + 1], __fmul_rn(2.0f, d1)), esq);
                if (dd0 < bestv[ii])     { bestv[ii]     = dd0; besti[ii]     = k; }
                if (dd1 < bestv[ii + 1]) { bestv[ii + 1] = dd1; besti[ii + 1] = k; }
            }
        }
    }

    // cross-lane argmin over the 16 code lanes (first-index ties)
    #pragma unroll
    for (int off = 1; off < 16; off <<= 1) {
        #pragma unroll
        for (int i = 0; i < 8; ++i) {
            float ov = __shfl_xor_sync(0xffffffffu, bestv[i], off);
            int   oi = __shfl_xor_sync(0xffffffffu, besti[i], off);
            if (ov < bestv[i] || (ov == bestv[i] && oi < besti[i])) { bestv[i] = ov; besti[i] = oi; }
        }
    }
    if (tc == 0) {
        #pragma unroll
        for (int i = 0; i < 8; ++i) {
            int p = tr * 8 + i;
            idxs[p] = besti[i];
            out[OFF_IDX + n0 + p] = (float)besti[i];
            atomicAdd(&g_hist[besti[i]], 1u);
        }
    }
    __syncthreads();   // idxs visible; es/xs readers of mainloop done

    // ---- fused quantize + straight-through + loss (xs still resident) ----
    {
        const int p = t >> 1;          // 0..127
        const int h = t & 1;           // channel half
        const int c0 = 32 * h;
        const int k = idxs[p];
        const float* eb = emb + (size_t)k * CD + c0;
        float* ob = out + (size_t)(n0 + p) * CD + c0;
        const float* xcol = xs + c0 * XSTRIDE + p;

        double s = 0.0;
        #pragma unroll
        for (int j = 0; j < 8; ++j) {
            float4 qv = __ldg(reinterpret_cast<const float4*>(eb) + j);
            float x0 = xcol[(4 * j + 0) * XSTRIDE];
            float x1 = xcol[(4 * j + 1) * XSTRIDE];
            float x2 = xcol[(4 * j + 2) * XSTRIDE];
            float x3 = xcol[(4 * j + 3) * XSTRIDE];
            float e0 = __fsub_rn(qv.x, x0);
            float e1 = __fsub_rn(qv.y, x1);
            float e2 = __fsub_rn(qv.z, x2);
            float e3 = __fsub_rn(qv.w, x3);
            float4 o;  // straight-through: x + (q - x)
            o.x = __fadd_rn(x0, e0);
            o.y = __fadd_rn(x1, e1);
            o.z = __fadd_rn(x2, e2);
            o.w = __fadd_rn(x3, e3);
            *reinterpret_cast<float4*>(ob + 4 * j) = o;
            s += (double)__fmul_rn(e0, e0) + (double)__fmul_rn(e1, e1)
               + (double)__fmul_rn(e2, e2) + (double)__fmul_rn(e3, e3);
        }
        // block-reduce the loss partial
        #pragma unroll
        for (int off = 16; off > 0; off >>= 1)
            s += __shfl_down_sync(0xffffffffu, s, off);
        if ((t & 31) == 0) red[t >> 5] = s;
        __syncthreads();
        if (t == 0) {
            double tot = 0.0;
            #pragma unroll
            for (int w = 0; w < 8; ++w) tot += red[w];
            atomicAdd(&g_loss, tot);
        }
    }
}

// ---------------- finalize ----------------
__global__ void vq_final(float* __restrict__ out) {
    __shared__ double red[256];
    int t = threadIdx.x;
    double s = 0.0;
    for (int k = t; k < KC; k += 256) {
        float cnt = (float)g_hist[k];
        float pr  = __fmul_rn(cnt, 1.0f / 65536.0f);
        float lg  = logf(__fadd_rn(pr, 1e-10f));
        s += (double)__fmul_rn(pr, lg);
    }
    red[t] = s;
    __syncthreads();
    for (int off = 128; off > 0; off >>= 1) {
        if (t < off) red[t] += red[t + off];
        __syncthreads();
    }
    if (t == 0) {
        float m = (float)(g_loss / 4194304.0);
        out[OFF_LOSS] = __fadd_rn(m, __fmul_rn(0.25f, m));
        out[OFF_PERP] = expf(-(float)red[0]);
    }
}

extern "C" void kernel_launch(void* const* d_in, const int* in_sizes, int n_in,
                              void* d_out, int out_size) {
    const float* inputs = (const float*)d_in[0];
    const float* emb    = (const float*)d_in[1];
    if (n_in >= 2 && in_sizes[0] == KC * CD && in_sizes[1] == NPTS * CD) {
        const float* tmp = inputs; inputs = emb; emb = tmp;
    }
    float* out = (float*)d_out;

    cudaFuncSetAttribute(vq_main, cudaFuncAttributeMaxDynamicSharedMemorySize, SMEM_BYTES);

    vq_init<<<1, 1024>>>();
    vq_esq<<<KC / 256, 256>>>(emb);
    vq_main<<<NPTS / MT, 256, SMEM_BYTES>>>(inputs, emb, out);
    vq_final<<<1, 256>>>(out);
}